// round 10
// baseline (speedup 1.0000x reference)
#include <cuda_runtime.h>
#include <math.h>

#define NPTS 16384
#define NCELL 24
#define NCELL3 13824
#define INV_CELL 0.1875f            // NCELL / 128
#define CELLSZ 5.3333333f           // 128 / NCELL
#define CAP 8                       // slots per cell (P(overflow) ~ 3e-6/cell)
#define OVF_CAP 1024
#define QBLK 256                    // 8 query-warps per block
#define NQBLK (2 * NPTS / 8)        // 4096 blocks

__device__ int    g_ccnt[2][NCELL3];
__device__ float4 g_slots[2][NCELL3 * CAP];   // w = -0.5*||p||^2
__device__ int    g_ovfn[2];
__device__ float4 g_ovf[2][OVF_CAP];
__device__ float  g_acc;
__device__ int    g_done;

// ---- build: bin points into fixed-capacity cells (no scan, no sort) ----
__global__ void build_kernel(const float* __restrict__ A,
                             const float* __restrict__ B) {
    int i = blockIdx.x * blockDim.x + threadIdx.x;   // 0 .. 2*NPTS-1
    int set = i >> 14;
    int idx = i & (NPTS - 1);
    const float* __restrict__ P = set ? B : A;
    float x = P[3 * idx], y = P[3 * idx + 1], z = P[3 * idx + 2];
    int cx = min((int)(x * INV_CELL), NCELL - 1);
    int cy = min((int)(y * INV_CELL), NCELL - 1);
    int cz = min((int)(z * INV_CELL), NCELL - 1);
    int c = (cx * NCELL + cy) * NCELL + cz;
    float4 pt = make_float4(x, y, z, -0.5f * (x * x + y * y + z * z));
    int pos = atomicAdd(&g_ccnt[set][c], 1);
    if (pos < CAP) {
        g_slots[set][c * CAP + pos] = pt;
    } else {
        int o = atomicAdd(&g_ovfn[set], 1);
        if (o < OVF_CAP) g_ovf[set][o] = pt;
    }
}

// ---- query: one warp per query; lane k < 27 owns neighborhood cell k ----
__global__ __launch_bounds__(QBLK) void query_kernel(const float* __restrict__ A,
                                                     const float* __restrict__ B,
                                                     float* __restrict__ out) {
    __shared__ float red[QBLK / 32];
    int warp = threadIdx.x >> 5;
    int lane = threadIdx.x & 31;
    int i = blockIdx.x * (QBLK / 32) + warp;   // query id 0 .. 2*NPTS-1
    int qs = i >> 14;
    int rs = qs ^ 1;
    int idx = i & (NPTS - 1);

    const float* __restrict__ Q = qs ? B : A;
    float x = Q[3 * idx], y = Q[3 * idx + 1], z = Q[3 * idx + 2];
    float qw = -0.5f * (x * x + y * y + z * z);
    int qx = min((int)(x * INV_CELL), NCELL - 1);
    int qy = min((int)(y * INV_CELL), NCELL - 1);
    int qz = min((int)(z * INV_CELL), NCELL - 1);

    const int* __restrict__ ccnt = g_ccnt[rs];
    const float4* __restrict__ slots = g_slots[rs];

    float best = -1e30f;   // max over refs of e = q.r - 0.5*||r||^2

    // radius-1: 27 cells, one per lane (lanes 27-31 idle)
    if (lane < 27) {
        int ix = qx + lane / 9 - 1;
        int iy = qy + (lane % 9) / 3 - 1;
        int iz = qz + lane % 3 - 1;
        if (ix >= 0 && ix < NCELL && iy >= 0 && iy < NCELL &&
            iz >= 0 && iz < NCELL) {
            int c = (ix * NCELL + iy) * NCELL + iz;
            int n = min(ccnt[c], CAP);
            const float4* s = slots + c * CAP;
            for (int j = 0; j < n; j++) {
                float4 t = s[j];
                float e = fmaf(x, t.x, fmaf(y, t.y, fmaf(z, t.z, t.w)));
                best = fmaxf(best, e);
            }
        }
    }

    // overflow points (expected ~0): every query must consider them
    {
        int no = min(g_ovfn[rs], OVF_CAP);
        for (int o = lane; o < no; o += 32) {
            float4 t = g_ovf[rs][o];
            float e = fmaf(x, t.x, fmaf(y, t.y, fmaf(z, t.z, t.w)));
            best = fmaxf(best, e);
        }
    }

    // warp max -> all lanes
    #pragma unroll
    for (int o = 16; o > 0; o >>= 1)
        best = fmaxf(best, __shfl_xor_sync(0xFFFFFFFFu, best, o));
    float d2 = -2.0f * (qw + best);

    // rare expansion (~0.7% of queries); warp-uniform control flow
    for (int r = 2; r <= NCELL; r++) {
        float rb = (r - 1) * CELLSZ;
        if (d2 <= rb * rb) break;    // all unscanned points strictly farther
        int x0 = max(qx - r, 0), x1 = min(qx + r, NCELL - 1);
        int y0 = max(qy - r, 0), y1 = min(qy + r, NCELL - 1);
        int z0 = max(qz - r, 0), z1 = min(qz + r, NCELL - 1);
        int k = 0;
        for (int ix = x0; ix <= x1; ix++)
            for (int iy = y0; iy <= y1; iy++)
                for (int iz = z0; iz <= z1; iz++) {
                    if ((k++ & 31) == lane) {
                        int c = (ix * NCELL + iy) * NCELL + iz;
                        int n = min(ccnt[c], CAP);
                        const float4* s = slots + c * CAP;
                        for (int j = 0; j < n; j++) {
                            float4 t = s[j];
                            float e = fmaf(x, t.x,
                                      fmaf(y, t.y, fmaf(z, t.z, t.w)));
                            best = fmaxf(best, e);
                        }
                    }
                }
        #pragma unroll
        for (int o = 16; o > 0; o >>= 1)
            best = fmaxf(best, __shfl_xor_sync(0xFFFFFFFFu, best, o));
        d2 = -2.0f * (qw + best);
    }

    // per-warp result -> block sum -> global atomic
    float v = sqrtf(fmaxf(d2, 0.0f));
    if (lane == 0) red[warp] = v;
    __syncthreads();
    if (threadIdx.x == 0) {
        float bs = 0.0f;
        #pragma unroll
        for (int w = 0; w < QBLK / 32; w++) bs += red[w];
        atomicAdd(&g_acc, bs);
        __threadfence();
        int t = atomicAdd(&g_done, 1);
        if (t == NQBLK - 1) {
            float total = *((volatile float*)&g_acc);
            out[0] = total * (1.0f / (2.0f * NPTS));
            // reset ALL state for the next graph replay
            g_acc = 0.0f;
            g_done = 0;
            g_ovfn[0] = 0;
            g_ovfn[1] = 0;
        }
    }
    // distributed reset of cell counts is unsafe mid-kernel (other blocks read),
    // so the last block does it after the output write:
    if (threadIdx.x < QBLK) {
        // only executes usefully in the last block; guard via g_done reset above
    }
}

// last-block count reset must happen after every reader is done; do it in a
// tiny trailing kernel-free way: fold into query's last block.
// (Implemented here as a follow-up pass inside the same kernel via the
//  arrival counter — see below in launch order.)

// Simpler and race-free: dedicated reset by the last arriving block.
// To keep it in ONE kernel, we re-open the last-block path:
__global__ void reset_kernel() {
    // zero cell counts for the next replay (both sets)
    int i = blockIdx.x * blockDim.x + threadIdx.x;
    if (i < 2 * NCELL3) ((int*)g_ccnt)[i] = 0;
}

extern "C" void kernel_launch(void* const* d_in, const int* in_sizes, int n_in,
                              void* d_out, int out_size) {
    const float* a = (const float*)d_in[0];
    const float* b = (const float*)d_in[1];
    float* out = (float*)d_out;

    build_kernel<<<(2 * NPTS) / 256, 256>>>(a, b);
    query_kernel<<<NQBLK, QBLK>>>(a, b, out);
    // runs concurrently-after query in-stream; zeroes counts for next replay
    reset_kernel<<<(2 * NCELL3 + 255) / 256, 256>>>();
}